// round 1
// baseline (speedup 1.0000x reference)
#include <cuda_runtime.h>
#include <math.h>

#define BB 2
#define CC 768
#define NBLK 8
#define BSZ 96
#define HH 32
#define WW 32
#define DD 32
#define DR 17
#define MODES 17408              /* 32*32*17 */
#define NLINES 1572864           /* 2*768*32*32 */
#define SLABS 1536               /* 2*768 */
#define S1 0.0055242717280199026f /* 1/sqrt(32768) */
#define LAMBDA 0.01f
#define GEMM_TILE 32

// Scratch: spectral buffers (allowed: __device__ globals, no runtime alloc)
__device__ float2 g_Xf[26738688];
__device__ float2 g_Yf[26738688];

__constant__ float TWC[16] = {
  1.0f, 0.9807852804032304f, 0.9238795325112867f, 0.8314696123025452f,
  0.7071067811865476f, 0.5555702330196022f, 0.3826834323650898f, 0.19509032201612827f,
  0.0f, -0.19509032201612827f, -0.3826834323650898f, -0.5555702330196022f,
  -0.7071067811865476f, -0.8314696123025452f, -0.9238795325112867f, -0.9807852804032304f
};
__constant__ float TWS[16] = {
  0.0f, 0.19509032201612827f, 0.3826834323650898f, 0.5555702330196022f,
  0.7071067811865476f, 0.8314696123025452f, 0.9238795325112867f, 0.9807852804032304f,
  1.0f, 0.9807852804032304f, 0.9238795325112867f, 0.8314696123025452f,
  0.7071067811865476f, 0.5555702330196022f, 0.3826834323650898f, 0.19509032201612827f
};

// Fully-unrolled in-register 32-point radix-2 FFT (DIT).
// Forward: exp(-i*2pi*k/32). Inverse: conj twiddles, NO 1/N scaling.
template<bool INV>
__device__ __forceinline__ void fft32(float2* v) {
  constexpr int br[32] = {0,16,8,24,4,20,12,28,2,18,10,26,6,22,14,30,
                          1,17,9,25,5,21,13,29,3,19,11,27,7,23,15,31};
  #pragma unroll
  for (int i = 0; i < 32; i++) {
    int j = br[i];
    if (j > i) { float2 tmp = v[i]; v[i] = v[j]; v[j] = tmp; }
  }
  #pragma unroll
  for (int s = 1; s <= 5; s++) {
    const int m = 1 << s;
    const int hm = m >> 1;
    #pragma unroll
    for (int j = 0; j < hm; j++) {
      const int ti = j << (5 - s);
      const float wr = TWC[ti];
      const float wi = INV ? TWS[ti] : -TWS[ti];
      #pragma unroll
      for (int k = j; k < 32; k += m) {
        float2 a = v[k], b = v[k + hm];
        float tr = fmaf(b.x, wr, -b.y * wi);
        float tq = fmaf(b.x, wi,  b.y * wr);
        v[k]      = make_float2(a.x + tr, a.y + tq);
        v[k + hm] = make_float2(a.x - tr, a.y - tq);
      }
    }
  }
}

// ---------------- Pass 1: rFFT along D + full ortho scale ----------------
__global__ void __launch_bounds__(256) k_rfft_d(const float* __restrict__ x) {
  __shared__ float sIn[8][32][33];
  const int t = threadIdx.x, warp = t >> 5, lane = t & 31;
  const long long lineBase = (long long)blockIdx.x * 256 + warp * 32;
  const float* src = x + lineBase * DD;
  #pragma unroll
  for (int r = 0; r < 32; r++) sIn[warp][r][lane] = src[r * 32 + lane];
  __syncwarp();
  float2 v[32];
  #pragma unroll
  for (int d = 0; d < 32; d++) v[d] = make_float2(sIn[warp][lane][d], 0.0f);
  fft32<false>(v);
  const long long ob = (lineBase + lane) * DR;
  #pragma unroll
  for (int k = 0; k < DR; k++)
    g_Xf[ob + k] = make_float2(v[k].x * S1, v[k].y * S1);
}

// ---------------- Passes 2/4: W then H FFT, whole slab in smem ----------------
template<bool INV, bool USEY>
__global__ void __launch_bounds__(256) k_fft_wh() {
  extern __shared__ float2 sm[];
  float2* data = USEY ? g_Yf : g_Xf;
  const long long base = (long long)blockIdx.x * MODES;
  const int t = threadIdx.x;
  for (int idx = t; idx < MODES; idx += 256) sm[idx] = data[base + idx];
  __syncthreads();
  // FFT along W: lines indexed by (h, d')
  for (int li = t; li < 544; li += 256) {
    const int h = li / 17, dp = li % 17;
    float2 v[32];
    #pragma unroll
    for (int w = 0; w < 32; w++) v[w] = sm[h * 544 + w * 17 + dp];
    fft32<INV>(v);
    #pragma unroll
    for (int w = 0; w < 32; w++) sm[h * 544 + w * 17 + dp] = v[w];
  }
  __syncthreads();
  // FFT along H: lines indexed by q = w*17+d'
  for (int li = t; li < 544; li += 256) {
    float2 v[32];
    #pragma unroll
    for (int h = 0; h < 32; h++) v[h] = sm[h * 544 + li];
    fft32<INV>(v);
    #pragma unroll
    for (int h = 0; h < 32; h++) sm[h * 544 + li] = v[h];
  }
  __syncthreads();
  for (int idx = t; idx < MODES; idx += 256) data[base + idx] = sm[idx];
}

// ---------------- Pass 3: fused complex GEMM1+GELU+GEMM2+softshrink ----------------
__device__ __forceinline__ float geluf(float v) {
  return 0.5f * v * (1.0f + erff(v * 0.7071067811865476f));
}
__device__ __forceinline__ float sshrink(float v) {
  float a = fabsf(v) - LAMBDA;
  return a > 0.0f ? copysignf(a, v) : 0.0f;
}

__global__ void __launch_bounds__(256) k_cgemm(
    const float* __restrict__ w1r, const float* __restrict__ w1i,
    const float* __restrict__ w2r, const float* __restrict__ w2i,
    const float* __restrict__ b1r, const float* __restrict__ b1i,
    const float* __restrict__ b2r, const float* __restrict__ b2i) {
  extern __shared__ float2 smg[];
  float2* W1s = smg;                  // 9216
  float2* W2s = W1s + 9216;           // 9216
  float2* Xs  = W2s + 9216;           // 96*GEMM_TILE (reused as H1 buffer)
  float2* B1s = Xs + 96 * GEMM_TILE;  // 96
  float2* B2s = B1s + 96;             // 96
  const int n = blockIdx.y;
  const int tile = blockIdx.x;        // 0..1087 (tiles never cross batch: 17408/32 = 544)
  const int b = tile / 544;
  const int m0 = (tile % 544) * GEMM_TILE;
  const int t = threadIdx.x;
  const int wb = n * 9216;
  for (int idx = t; idx < 9216; idx += 256) {
    W1s[idx] = make_float2(w1r[wb + idx], w1i[wb + idx]);
    W2s[idx] = make_float2(w2r[wb + idx], w2i[wb + idx]);
  }
  if (t < 96) {
    B1s[t] = make_float2(b1r[n * 96 + t], b1i[n * 96 + t]);
    B2s[t] = make_float2(b2r[n * 96 + t], b2i[n * 96 + t]);
  }
  const long long chbase = ((long long)b * CC + (long long)n * BSZ) * MODES + m0;
  for (int idx = t; idx < 96 * GEMM_TILE; idx += 256) {
    const int i = idx >> 5, mo = idx & 31;
    Xs[idx] = g_Xf[chbase + (long long)i * MODES + mo];
  }
  __syncthreads();

  const int mo = t & 31, og = t >> 5; // 32 mode-threads x 8 o-groups, 12 outputs each
  float2 acc[12];
  #pragma unroll
  for (int j = 0; j < 12; j++) acc[j] = B1s[og * 12 + j];
  #pragma unroll 2
  for (int k = 0; k < 96; k++) {
    const float2 xv = Xs[k * GEMM_TILE + mo];
    #pragma unroll
    for (int j = 0; j < 12; j++) {
      const float2 w = W1s[k * 96 + og * 12 + j];
      acc[j].x = fmaf(xv.x, w.x, acc[j].x);
      acc[j].x = fmaf(-xv.y, w.y, acc[j].x);
      acc[j].y = fmaf(xv.x, w.y, acc[j].y);
      acc[j].y = fmaf(xv.y, w.x, acc[j].y);
    }
  }
  __syncthreads();   // everyone done reading Xs
  #pragma unroll
  for (int j = 0; j < 12; j++)
    Xs[(og * 12 + j) * GEMM_TILE + mo] =
        make_float2(geluf(acc[j].x), geluf(acc[j].y));
  __syncthreads();   // H1 visible
  #pragma unroll
  for (int j = 0; j < 12; j++) acc[j] = B2s[og * 12 + j];
  #pragma unroll 2
  for (int k = 0; k < 96; k++) {
    const float2 xv = Xs[k * GEMM_TILE + mo];
    #pragma unroll
    for (int j = 0; j < 12; j++) {
      const float2 w = W2s[k * 96 + og * 12 + j];
      acc[j].x = fmaf(xv.x, w.x, acc[j].x);
      acc[j].x = fmaf(-xv.y, w.y, acc[j].x);
      acc[j].y = fmaf(xv.x, w.y, acc[j].y);
      acc[j].y = fmaf(xv.y, w.x, acc[j].y);
    }
  }
  #pragma unroll
  for (int j = 0; j < 12; j++) {
    const int o = og * 12 + j;
    g_Yf[chbase + (long long)o * MODES + mo] =
        make_float2(sshrink(acc[j].x), sshrink(acc[j].y));
  }
}

// ---------------- Pass 5: inverse rFFT along D + scale + residual ----------------
__global__ void __launch_bounds__(256) k_irfft_d(const float* __restrict__ x,
                                                 float* __restrict__ out) {
  __shared__ float sOut[8][32][33];
  const int t = threadIdx.x, warp = t >> 5, lane = t & 31;
  const long long lineBase = (long long)blockIdx.x * 256 + warp * 32;
  float2 v[32];
  const long long ib = (lineBase + lane) * DR;
  #pragma unroll
  for (int k = 0; k < DR; k++) v[k] = g_Yf[ib + k];
  #pragma unroll
  for (int k = DR; k < 32; k++) {
    const float2 z = v[32 - k];
    v[k] = make_float2(z.x, -z.y);
  }
  fft32<true>(v);
  #pragma unroll
  for (int d = 0; d < 32; d++) sOut[warp][lane][d] = v[d].x * S1;
  __syncwarp();
  const long long gb = lineBase * 32;
  #pragma unroll
  for (int r = 0; r < 32; r++)
    out[gb + r * 32 + lane] = sOut[warp][r][lane] + x[gb + r * 32 + lane];
}

// ---------------- launch ----------------
extern "C" void kernel_launch(void* const* d_in, const int* in_sizes, int n_in,
                              void* d_out, int out_size) {
  const float* x   = (const float*)d_in[0];
  const float* w1r = (const float*)d_in[1];
  const float* w1i = (const float*)d_in[2];
  const float* w2r = (const float*)d_in[3];
  const float* w2i = (const float*)d_in[4];
  const float* b1r = (const float*)d_in[5];
  const float* b1i = (const float*)d_in[6];
  const float* b2r = (const float*)d_in[7];
  const float* b2i = (const float*)d_in[8];
  float* out = (float*)d_out;

  const int slabBytes = MODES * (int)sizeof(float2);                         // 139264
  const int gemmBytes = (9216 * 2 + 96 * GEMM_TILE + 192) * (int)sizeof(float2); // 173568

  cudaFuncSetAttribute(k_fft_wh<false, false>,
                       cudaFuncAttributeMaxDynamicSharedMemorySize, slabBytes);
  cudaFuncSetAttribute(k_fft_wh<true, true>,
                       cudaFuncAttributeMaxDynamicSharedMemorySize, slabBytes);
  cudaFuncSetAttribute(k_cgemm,
                       cudaFuncAttributeMaxDynamicSharedMemorySize, gemmBytes);

  k_rfft_d<<<NLINES / 256, 256>>>(x);
  k_fft_wh<false, false><<<SLABS, 256, slabBytes>>>();
  dim3 g3(1088, NBLK);
  k_cgemm<<<g3, 256, gemmBytes>>>(w1r, w1i, w2r, w2i, b1r, b1i, b2r, b2i);
  k_fft_wh<true, true><<<SLABS, 256, slabBytes>>>();
  k_irfft_d<<<NLINES / 256, 256>>>(x, out);
}

// round 2
// speedup vs baseline: 2.9019x; 2.9019x over previous
#include <cuda_runtime.h>
#include <cuda_bf16.h>
#include <math.h>
#include <stdint.h>

#define CC 768
#define NBLK 8
#define DR 17
#define MODES 17408              /* 17*32*32, layout [d'][h][w] */
#define NLINES 1572864           /* 2*768*32*32 */
#define NPLANES 26112            /* 1536*17 */
#define S1 0.0055242717280199026f /* 1/sqrt(32768) */
#define LAMBDA 0.01f
#define KP 200                   /* padded K stride (bf16) for A/W tiles */
#define STG 193                  /* padded fp32 staging stride */

__device__ float2 g_Xf[26738688];
__device__ float2 g_Yf[26738688];

__constant__ float TWC[16] = {
  1.0f, 0.9807852804032304f, 0.9238795325112867f, 0.8314696123025452f,
  0.7071067811865476f, 0.5555702330196022f, 0.3826834323650898f, 0.19509032201612827f,
  0.0f, -0.19509032201612827f, -0.3826834323650898f, -0.5555702330196022f,
  -0.7071067811865476f, -0.8314696123025452f, -0.9238795325112867f, -0.9807852804032304f
};
__constant__ float TWS[16] = {
  0.0f, 0.19509032201612827f, 0.3826834323650898f, 0.5555702330196022f,
  0.7071067811865476f, 0.8314696123025452f, 0.9238795325112867f, 0.9807852804032304f,
  1.0f, 0.9807852804032304f, 0.9238795325112867f, 0.8314696123025452f,
  0.7071067811865476f, 0.5555702330196022f, 0.3826834323650898f, 0.19509032201612827f
};

template<bool INV>
__device__ __forceinline__ void fft32(float2* v) {
  constexpr int br[32] = {0,16,8,24,4,20,12,28,2,18,10,26,6,22,14,30,
                          1,17,9,25,5,21,13,29,3,19,11,27,7,23,15,31};
  #pragma unroll
  for (int i = 0; i < 32; i++) {
    int j = br[i];
    if (j > i) { float2 tmp = v[i]; v[i] = v[j]; v[j] = tmp; }
  }
  #pragma unroll
  for (int s = 1; s <= 5; s++) {
    const int m = 1 << s, hm = m >> 1;
    #pragma unroll
    for (int j = 0; j < hm; j++) {
      const int ti = j << (5 - s);
      const float wr = TWC[ti];
      const float wi = INV ? TWS[ti] : -TWS[ti];
      #pragma unroll
      for (int k = j; k < 32; k += m) {
        float2 a = v[k], b = v[k + hm];
        float tr = fmaf(b.x, wr, -b.y * wi);
        float tq = fmaf(b.x, wi,  b.y * wr);
        v[k]      = make_float2(a.x + tr, a.y + tq);
        v[k + hm] = make_float2(a.x - tr, a.y - tq);
      }
    }
  }
}

// ---------------- Pass 1: rFFT along D -> plane-major spectral layout ----------------
__global__ void __launch_bounds__(256) k_rfft_d(const float* __restrict__ x) {
  __shared__ float sIn[8][32][33];
  const int t = threadIdx.x, warp = t >> 5, lane = t & 31;
  const int line0 = blockIdx.x * 256 + warp * 32;
  const float* src = x + (long long)line0 * 32;
  #pragma unroll
  for (int r = 0; r < 32; r++) sIn[warp][r][lane] = src[r * 32 + lane];
  __syncwarp();
  float2 v[32];
  #pragma unroll
  for (int d = 0; d < 32; d++) v[d] = make_float2(sIn[warp][lane][d], 0.0f);
  fft32<false>(v);
  const int bc = line0 >> 10, h = (line0 >> 5) & 31;
  const long long ob = (long long)bc * MODES + h * 32 + lane;  // w = lane
  #pragma unroll
  for (int k = 0; k < DR; k++)
    g_Xf[ob + k * 1024] = make_float2(v[k].x * S1, v[k].y * S1);
}

// ---------------- Passes 2/4: W+H FFT, one warp per 32x32 plane ----------------
template<bool INV, bool USEY>
__global__ void __launch_bounds__(256) k_fft_wh() {
  extern __shared__ float2 sm[];               // 8 planes x [32][33]
  float2* data = USEY ? g_Yf : g_Xf;
  const int t = threadIdx.x, p = t >> 5, lane = t & 31;
  float2* pl = sm + p * 1056;
  const long long pb = (long long)(blockIdx.x * 8 + p) * 1024;
  #pragma unroll
  for (int i = 0; i < 32; i++) pl[i * 33 + lane] = data[pb + i * 32 + lane];
  __syncwarp();
  float2 v[32];
  // FFT along W (rows)
  #pragma unroll
  for (int w = 0; w < 32; w++) v[w] = pl[lane * 33 + w];
  fft32<INV>(v);
  #pragma unroll
  for (int w = 0; w < 32; w++) pl[lane * 33 + w] = v[w];
  __syncwarp();
  // FFT along H (cols)
  #pragma unroll
  for (int h = 0; h < 32; h++) v[h] = pl[h * 33 + lane];
  fft32<INV>(v);
  #pragma unroll
  for (int h = 0; h < 32; h++) pl[h * 33 + lane] = v[h];
  __syncwarp();
  #pragma unroll
  for (int i = 0; i < 32; i++) data[pb + i * 32 + lane] = pl[i * 33 + lane];
}

// ---------------- Pass 3: bf16 tensor-core fused channel MLP ----------------
__device__ __forceinline__ float geluf(float v) {
  return 0.5f * v * (1.0f + erff(v * 0.7071067811865476f));
}
__device__ __forceinline__ float sshrink(float v) {
  float a = fabsf(v) - LAMBDA;
  return a > 0.0f ? copysignf(a, v) : 0.0f;
}
__device__ __forceinline__ uint32_t sptr(const void* p) {
  return (uint32_t)__cvta_generic_to_shared(p);
}
__device__ __forceinline__ void ldm4(uint32_t a, uint32_t& r0, uint32_t& r1,
                                     uint32_t& r2, uint32_t& r3) {
  asm volatile("ldmatrix.sync.aligned.m8n8.x4.shared.b16 {%0,%1,%2,%3},[%4];\n"
               : "=r"(r0), "=r"(r1), "=r"(r2), "=r"(r3) : "r"(a));
}
__device__ __forceinline__ void mma16816(float* d, const uint32_t* a,
                                         uint32_t b0, uint32_t b1) {
  asm volatile(
    "mma.sync.aligned.m16n8k16.row.col.f32.bf16.bf16.f32 "
    "{%0,%1,%2,%3},{%4,%5,%6,%7},{%8,%9},{%0,%1,%2,%3};\n"
    : "+f"(d[0]), "+f"(d[1]), "+f"(d[2]), "+f"(d[3])
    : "r"(a[0]), "r"(a[1]), "r"(a[2]), "r"(a[3]), "r"(b0), "r"(b1));
}

__device__ __forceinline__ void gemm192(const __nv_bfloat16* __restrict__ As,
                                        const __nv_bfloat16* __restrict__ Ws,
                                        int mwo, int nwo, int lrow, int lcolh,
                                        float acc[2][12][4]) {
  #pragma unroll
  for (int mt = 0; mt < 2; mt++)
    #pragma unroll
    for (int nt = 0; nt < 12; nt++)
      #pragma unroll
      for (int e = 0; e < 4; e++) acc[mt][nt][e] = 0.0f;
  #pragma unroll 1
  for (int ks = 0; ks < 12; ks++) {
    const int k0 = ks * 16;
    uint32_t a[2][4];
    #pragma unroll
    for (int mt = 0; mt < 2; mt++)
      ldm4(sptr(As + (mwo + mt * 16 + lrow) * KP + k0 + lcolh),
           a[mt][0], a[mt][1], a[mt][2], a[mt][3]);
    #pragma unroll
    for (int p = 0; p < 6; p++) {
      uint32_t r0, r1, r2, r3;
      ldm4(sptr(Ws + (nwo + p * 16 + lrow) * KP + k0 + lcolh), r0, r1, r2, r3);
      #pragma unroll
      for (int mt = 0; mt < 2; mt++) {
        mma16816(acc[mt][2 * p],     a[mt], r0, r2);
        mma16816(acc[mt][2 * p + 1], a[mt], r1, r3);
      }
    }
  }
}

__global__ void __launch_bounds__(256) k_cgemm(
    const float* __restrict__ w1r, const float* __restrict__ w1i,
    const float* __restrict__ w2r, const float* __restrict__ w2i,
    const float* __restrict__ b1r, const float* __restrict__ b1i,
    const float* __restrict__ b2r, const float* __restrict__ b2i) {
  extern __shared__ char smraw[];
  __nv_bfloat16* As  = (__nv_bfloat16*)smraw;   // [128][KP]
  __nv_bfloat16* W1s = As + 128 * KP;           // [192][KP]
  __nv_bfloat16* W2s = W1s + 192 * KP;          // [192][KP]
  float* b1s = (float*)(W2s + 192 * KP);        // [192]
  float* b2s = b1s + 192;
  float* stg = (float*)W1s;                     // reused fp32 [128][STG]

  const int t = threadIdx.x;
  const int m0 = blockIdx.x * 128;
  const int b  = blockIdx.y;
  const int nb = blockIdx.z;
  const int wb = nb * 9216;

  // Expand complex weights into 192x192 real form: [[Wr, Wi],[-Wi, Wr]] transposed to [n][k]
  for (int idx = t; idx < 9216; idx += 256) {
    const int i = idx / 96, o = idx % 96;
    const float r1v = w1r[wb + idx], i1v = w1i[wb + idx];
    const float r2v = w2r[wb + idx], i2v = w2i[wb + idx];
    W1s[o * KP + i]              = __float2bfloat16_rn(r1v);
    W1s[o * KP + i + 96]         = __float2bfloat16_rn(-i1v);
    W1s[(o + 96) * KP + i]       = __float2bfloat16_rn(i1v);
    W1s[(o + 96) * KP + i + 96]  = __float2bfloat16_rn(r1v);
    W2s[o * KP + i]              = __float2bfloat16_rn(r2v);
    W2s[o * KP + i + 96]         = __float2bfloat16_rn(-i2v);
    W2s[(o + 96) * KP + i]       = __float2bfloat16_rn(i2v);
    W2s[(o + 96) * KP + i + 96]  = __float2bfloat16_rn(r2v);
  }
  if (t < 192) {
    b1s[t] = (t < 96) ? b1r[nb * 96 + t] : b1i[nb * 96 + t - 96];
    b2s[t] = (t < 96) ? b2r[nb * 96 + t] : b2i[nb * 96 + t - 96];
  }
  // A tile: 128 modes x 96 complex channels -> [m][192] bf16
  const long long chbase = ((long long)b * CC + nb * 96) * MODES;
  for (int idx = t; idx < 12288; idx += 256) {
    const int i = idx >> 7, mm = idx & 127;
    const float2 xv = g_Xf[chbase + (long long)i * MODES + m0 + mm];
    As[mm * KP + i]      = __float2bfloat16_rn(xv.x);
    As[mm * KP + i + 96] = __float2bfloat16_rn(xv.y);
  }
  __syncthreads();

  const int lane = t & 31, wid = t >> 5;
  const int mwo = (wid & 3) * 32, nwo = (wid >> 2) * 96;
  const int lrow = lane & 15, lcolh = (lane >> 4) * 8;
  const int frow = lane >> 2, fcol = 2 * (lane & 3);

  float acc[2][12][4];
  gemm192(As, W1s, mwo, nwo, lrow, lcolh, acc);
  __syncthreads();              // all GEMM1 smem reads complete

  // epilogue 1: bias + exact GELU -> H1 into As (bf16)
  #pragma unroll
  for (int mt = 0; mt < 2; mt++) {
    #pragma unroll
    for (int nt = 0; nt < 12; nt++) {
      const int col = nwo + nt * 8 + fcol;
      const float bl = b1s[col], bh = b1s[col + 1];
      const int r0 = mwo + mt * 16 + frow;
      __nv_bfloat162 p0, p1;
      p0.x = __float2bfloat16_rn(geluf(acc[mt][nt][0] + bl));
      p0.y = __float2bfloat16_rn(geluf(acc[mt][nt][1] + bh));
      p1.x = __float2bfloat16_rn(geluf(acc[mt][nt][2] + bl));
      p1.y = __float2bfloat16_rn(geluf(acc[mt][nt][3] + bh));
      *(__nv_bfloat162*)(As + r0 * KP + col)       = p0;
      *(__nv_bfloat162*)(As + (r0 + 8) * KP + col) = p1;
    }
  }
  __syncthreads();              // H1 visible

  gemm192(As, W2s, mwo, nwo, lrow, lcolh, acc);
  __syncthreads();              // all GEMM2 smem reads complete (stg aliases W1s/W2s)

  // epilogue 2: bias + softshrink -> fp32 staging
  #pragma unroll
  for (int mt = 0; mt < 2; mt++) {
    #pragma unroll
    for (int nt = 0; nt < 12; nt++) {
      const int col = nwo + nt * 8 + fcol;
      const float bl = b2s[col], bh = b2s[col + 1];
      const int r0 = mwo + mt * 16 + frow;
      stg[r0 * STG + col]           = sshrink(acc[mt][nt][0] + bl);
      stg[r0 * STG + col + 1]       = sshrink(acc[mt][nt][1] + bh);
      stg[(r0 + 8) * STG + col]     = sshrink(acc[mt][nt][2] + bl);
      stg[(r0 + 8) * STG + col + 1] = sshrink(acc[mt][nt][3] + bh);
    }
  }
  __syncthreads();

  // coalesced store back to channel-major spectral buffer
  for (int idx = t; idx < 12288; idx += 256) {
    const int c = idx >> 7, mm = idx & 127;
    float2 o;
    o.x = stg[mm * STG + c];
    o.y = stg[mm * STG + c + 96];
    g_Yf[chbase + (long long)c * MODES + m0 + mm] = o;
  }
}

// ---------------- Pass 5: inverse rFFT along D + residual ----------------
__global__ void __launch_bounds__(256) k_irfft_d(const float* __restrict__ x,
                                                 float* __restrict__ out) {
  __shared__ float sOut[8][32][33];
  const int t = threadIdx.x, warp = t >> 5, lane = t & 31;
  const int line0 = blockIdx.x * 256 + warp * 32;
  const int bc = line0 >> 10, h = (line0 >> 5) & 31;
  float2 v[32];
  const long long ib = (long long)bc * MODES + h * 32 + lane;
  #pragma unroll
  for (int k = 0; k < DR; k++) v[k] = g_Yf[ib + k * 1024];
  #pragma unroll
  for (int k = DR; k < 32; k++) {
    const float2 z = v[32 - k];
    v[k] = make_float2(z.x, -z.y);
  }
  fft32<true>(v);
  #pragma unroll
  for (int d = 0; d < 32; d++) sOut[warp][lane][d] = v[d].x * S1;
  __syncwarp();
  const long long gb = (long long)line0 * 32;
  #pragma unroll
  for (int r = 0; r < 32; r++)
    out[gb + r * 32 + lane] = sOut[warp][r][lane] + x[gb + r * 32 + lane];
}

// ---------------- launch ----------------
extern "C" void kernel_launch(void* const* d_in, const int* in_sizes, int n_in,
                              void* d_out, int out_size) {
  const float* x   = (const float*)d_in[0];
  const float* w1r = (const float*)d_in[1];
  const float* w1i = (const float*)d_in[2];
  const float* w2r = (const float*)d_in[3];
  const float* w2i = (const float*)d_in[4];
  const float* b1r = (const float*)d_in[5];
  const float* b1i = (const float*)d_in[6];
  const float* b2r = (const float*)d_in[7];
  const float* b2i = (const float*)d_in[8];
  float* out = (float*)d_out;

  const int fftBytes  = 8 * 1056 * (int)sizeof(float2);                 // 67584
  const int gemmBytes = (128 + 384) * KP * 2 + 384 * (int)sizeof(float); // 206336

  cudaFuncSetAttribute(k_fft_wh<false, false>,
                       cudaFuncAttributeMaxDynamicSharedMemorySize, fftBytes);
  cudaFuncSetAttribute(k_fft_wh<true, true>,
                       cudaFuncAttributeMaxDynamicSharedMemorySize, fftBytes);
  cudaFuncSetAttribute(k_cgemm,
                       cudaFuncAttributeMaxDynamicSharedMemorySize, gemmBytes);

  k_rfft_d<<<NLINES / 256, 256>>>(x);
  k_fft_wh<false, false><<<NPLANES / 8, 256, fftBytes>>>();
  dim3 g3(136, 2, NBLK);
  k_cgemm<<<g3, 256, gemmBytes>>>(w1r, w1i, w2r, w2i, b1r, b1i, b2r, b2i);
  k_fft_wh<true, true><<<NPLANES / 8, 256, fftBytes>>>();
  k_irfft_d<<<NLINES / 256, 256>>>(x, out);
}

// round 4
// speedup vs baseline: 3.0223x; 1.0415x over previous
#include <cuda_runtime.h>
#include <cuda_bf16.h>
#include <math.h>
#include <stdint.h>

#define CC 768
#define NBLK 8
#define DR 17
#define MODES 17408              /* 17*32*32, layout [d'][h][w] */
#define NLINES 1572864           /* 2*768*32*32 */
#define NPLANES 26112            /* 1536*17 */
#define S1 0.0055242717280199026f /* 1/sqrt(32768) */
#define LAMBDA 0.01f
#define KP 200                   /* padded bf16 K-stride in smem */

__device__ uint32_t g_Xb[26738688];          /* forward spectrum, bf16x2 */
__device__ float    g_Yr[26738688];          /* MLP output, planar re  */
__device__ float    g_Yi[26738688];          /* MLP output, planar im  */
__device__ __nv_bfloat16 g_Wexp[589824];     /* 8 blocks x 2 mats x 192x192 */

__constant__ float TWC[16] = {
  1.0f, 0.9807852804032304f, 0.9238795325112867f, 0.8314696123025452f,
  0.7071067811865476f, 0.5555702330196022f, 0.3826834323650898f, 0.19509032201612827f,
  0.0f, -0.19509032201612827f, -0.3826834323650898f, -0.5555702330196022f,
  -0.7071067811865476f, -0.8314696123025452f, -0.9238795325112867f, -0.9807852804032304f
};
__constant__ float TWS[16] = {
  0.0f, 0.19509032201612827f, 0.3826834323650898f, 0.5555702330196022f,
  0.7071067811865476f, 0.8314696123025452f, 0.9238795325112867f, 0.9807852804032304f,
  1.0f, 0.9807852804032304f, 0.9238795325112867f, 0.8314696123025452f,
  0.7071067811865476f, 0.5555702330196022f, 0.3826834323650898f, 0.19509032201612827f
};

template<bool INV>
__device__ __forceinline__ void fft32(float2* v) {
  constexpr int br[32] = {0,16,8,24,4,20,12,28,2,18,10,26,6,22,14,30,
                          1,17,9,25,5,21,13,29,3,19,11,27,7,23,15,31};
  #pragma unroll
  for (int i = 0; i < 32; i++) {
    int j = br[i];
    if (j > i) { float2 tmp = v[i]; v[i] = v[j]; v[j] = tmp; }
  }
  #pragma unroll
  for (int s = 1; s <= 5; s++) {
    const int m = 1 << s, hm = m >> 1;
    #pragma unroll
    for (int j = 0; j < hm; j++) {
      const int ti = j << (5 - s);
      const float wr = TWC[ti];
      const float wi = INV ? TWS[ti] : -TWS[ti];
      #pragma unroll
      for (int k = j; k < 32; k += m) {
        float2 a = v[k], b = v[k + hm];
        float tr = fmaf(b.x, wr, -b.y * wi);
        float tq = fmaf(b.x, wi,  b.y * wr);
        v[k]      = make_float2(a.x + tr, a.y + tq);
        v[k + hm] = make_float2(a.x - tr, a.y - tq);
      }
    }
  }
}

// ---------------- weight prep: expand to bf16 once ----------------
__global__ void k_wprep(const float* __restrict__ w1r, const float* __restrict__ w1i,
                        const float* __restrict__ w2r, const float* __restrict__ w2i) {
  const int nb = blockIdx.x, t = threadIdx.x;
  const int wb = nb * 9216;
  __nv_bfloat16* g1 = g_Wexp + nb * 73728;
  __nv_bfloat16* g2 = g1 + 36864;
  for (int idx = t; idx < 9216; idx += 256) {
    const int i = idx / 96, o = idx % 96;
    const float r1v = w1r[wb + idx], i1v = w1i[wb + idx];
    const float r2v = w2r[wb + idx], i2v = w2i[wb + idx];
    g1[o * 192 + i]              = __float2bfloat16_rn(r1v);
    g1[o * 192 + i + 96]         = __float2bfloat16_rn(-i1v);
    g1[(o + 96) * 192 + i]       = __float2bfloat16_rn(i1v);
    g1[(o + 96) * 192 + i + 96]  = __float2bfloat16_rn(r1v);
    g2[o * 192 + i]              = __float2bfloat16_rn(r2v);
    g2[o * 192 + i + 96]         = __float2bfloat16_rn(-i2v);
    g2[(o + 96) * 192 + i]       = __float2bfloat16_rn(i2v);
    g2[(o + 96) * 192 + i + 96]  = __float2bfloat16_rn(r2v);
  }
}

// ---------------- Pass 1: rFFT along D -> bf16 plane-major spectrum ----------------
__global__ void __launch_bounds__(256) k_rfft_d(const float* __restrict__ x) {
  __shared__ float sIn[8][32][33];
  const int t = threadIdx.x, warp = t >> 5, lane = t & 31;
  const int line0 = blockIdx.x * 256 + warp * 32;
  const float* src = x + (long long)line0 * 32;
  #pragma unroll
  for (int r = 0; r < 32; r++) sIn[warp][r][lane] = src[r * 32 + lane];
  __syncwarp();
  float2 v[32];
  #pragma unroll
  for (int d = 0; d < 32; d++) v[d] = make_float2(sIn[warp][lane][d], 0.0f);
  fft32<false>(v);
  const int bc = line0 >> 10, h = (line0 >> 5) & 31;
  const long long ob = (long long)bc * MODES + h * 32 + lane;
  #pragma unroll
  for (int k = 0; k < DR; k++) {
    __nv_bfloat162 pk = __float22bfloat162_rn(make_float2(v[k].x * S1, v[k].y * S1));
    g_Xb[ob + k * 1024] = *(uint32_t*)&pk;
  }
}

// ---------------- Pass 2: forward W+H FFT on bf16 buffer ----------------
__global__ void __launch_bounds__(256) k_fft_wh_fwd() {
  extern __shared__ float2 sm[];
  const int t = threadIdx.x, p = t >> 5, lane = t & 31;
  float2* pl = sm + p * 1056;
  const long long pb = (long long)(blockIdx.x * 8 + p) * 1024;
  #pragma unroll
  for (int i = 0; i < 32; i++) {
    uint32_t u = g_Xb[pb + i * 32 + lane];
    pl[i * 33 + lane] = __bfloat1622float2(*(__nv_bfloat162*)&u);
  }
  __syncwarp();
  float2 v[32];
  #pragma unroll
  for (int w = 0; w < 32; w++) v[w] = pl[lane * 33 + w];
  fft32<false>(v);
  #pragma unroll
  for (int w = 0; w < 32; w++) pl[lane * 33 + w] = v[w];
  __syncwarp();
  #pragma unroll
  for (int h = 0; h < 32; h++) v[h] = pl[h * 33 + lane];
  fft32<false>(v);
  #pragma unroll
  for (int h = 0; h < 32; h++) pl[h * 33 + lane] = v[h];
  __syncwarp();
  #pragma unroll
  for (int i = 0; i < 32; i++) {
    __nv_bfloat162 pk = __float22bfloat162_rn(pl[i * 33 + lane]);
    g_Xb[pb + i * 32 + lane] = *(uint32_t*)&pk;
  }
}

// ---------------- Pass 4: inverse W+H FFT on planar fp32 buffers ----------------
__global__ void __launch_bounds__(256) k_fft_wh_inv() {
  extern __shared__ float2 sm[];
  const int t = threadIdx.x, p = t >> 5, lane = t & 31;
  float2* pl = sm + p * 1056;
  const long long pb = (long long)(blockIdx.x * 8 + p) * 1024;
  #pragma unroll
  for (int i = 0; i < 32; i++)
    pl[i * 33 + lane] = make_float2(g_Yr[pb + i * 32 + lane],
                                    g_Yi[pb + i * 32 + lane]);
  __syncwarp();
  float2 v[32];
  #pragma unroll
  for (int w = 0; w < 32; w++) v[w] = pl[lane * 33 + w];
  fft32<true>(v);
  #pragma unroll
  for (int w = 0; w < 32; w++) pl[lane * 33 + w] = v[w];
  __syncwarp();
  #pragma unroll
  for (int h = 0; h < 32; h++) v[h] = pl[h * 33 + lane];
  fft32<true>(v);
  #pragma unroll
  for (int h = 0; h < 32; h++) pl[h * 33 + lane] = v[h];
  __syncwarp();
  #pragma unroll
  for (int i = 0; i < 32; i++) {
    const float2 o = pl[i * 33 + lane];
    g_Yr[pb + i * 32 + lane] = o.x;
    g_Yi[pb + i * 32 + lane] = o.y;
  }
}

// ---------------- Pass 3: pipelined HMMA fused channel MLP ----------------
__device__ __forceinline__ float geluf(float v) {
  return 0.5f * v * (1.0f + erff(v * 0.7071067811865476f));
}
__device__ __forceinline__ float sshrink(float v) {
  float a = fabsf(v) - LAMBDA;
  return a > 0.0f ? copysignf(a, v) : 0.0f;
}
__device__ __forceinline__ uint32_t sptr(const void* p) {
  return (uint32_t)__cvta_generic_to_shared(p);
}
__device__ __forceinline__ void ldm4(uint32_t a, uint32_t r[4]) {
  asm volatile("ldmatrix.sync.aligned.m8n8.x4.shared.b16 {%0,%1,%2,%3},[%4];\n"
               : "=r"(r[0]), "=r"(r[1]), "=r"(r[2]), "=r"(r[3]) : "r"(a));
}
__device__ __forceinline__ void mma16816(float* d, const uint32_t* a,
                                         uint32_t b0, uint32_t b1) {
  asm volatile(
    "mma.sync.aligned.m16n8k16.row.col.f32.bf16.bf16.f32 "
    "{%0,%1,%2,%3},{%4,%5,%6,%7},{%8,%9},{%0,%1,%2,%3};\n"
    : "+f"(d[0]), "+f"(d[1]), "+f"(d[2]), "+f"(d[3])
    : "r"(a[0]), "r"(a[1]), "r"(a[2]), "r"(a[3]), "r"(b0), "r"(b1));
}
__device__ __forceinline__ void loadfr(const uint16_t* As, const uint16_t* Ws,
                                       int arow0, int arow1, int wrow, int kc,
                                       uint32_t a[2][4], uint32_t w[6][4]) {
  ldm4(sptr(As + arow0 * KP + kc), a[0]);
  ldm4(sptr(As + arow1 * KP + kc), a[1]);
  #pragma unroll
  for (int p = 0; p < 6; p++)
    ldm4(sptr(Ws + (wrow + p * 16) * KP + kc), w[p]);
}
__device__ __forceinline__ void gemmPipe(const uint16_t* As, const uint16_t* Ws,
                                         int mwo, int nwo, int lrow, int lcolh,
                                         float acc[2][12][4]) {
  #pragma unroll
  for (int mt = 0; mt < 2; mt++)
    #pragma unroll
    for (int nt = 0; nt < 12; nt++)
      #pragma unroll
      for (int e = 0; e < 4; e++) acc[mt][nt][e] = 0.0f;
  const int arow0 = mwo + lrow, arow1 = mwo + 16 + lrow, wrow = nwo + lrow;
  uint32_t a[2][2][4], w[2][6][4];
  loadfr(As, Ws, arow0, arow1, wrow, lcolh, a[0], w[0]);
  #pragma unroll
  for (int ks = 0; ks < 12; ks++) {
    const int cur = ks & 1;
    if (ks < 11)
      loadfr(As, Ws, arow0, arow1, wrow, (ks + 1) * 16 + lcolh,
             a[cur ^ 1], w[cur ^ 1]);
    #pragma unroll
    for (int p = 0; p < 6; p++)
      #pragma unroll
      for (int mt = 0; mt < 2; mt++) {
        mma16816(acc[mt][2 * p],     a[cur][mt], w[cur][p][0], w[cur][p][2]);
        mma16816(acc[mt][2 * p + 1], a[cur][mt], w[cur][p][1], w[cur][p][3]);
      }
  }
}

#define OFF_AS 0
#define OFF_W1 51200
#define OFF_W2 128000
#define OFF_B1 204800
#define OFF_B2 205568
#define SM_TOTAL 206336

__global__ void __launch_bounds__(256, 1) k_cgemm(
    const float* __restrict__ b1r, const float* __restrict__ b1i,
    const float* __restrict__ b2r, const float* __restrict__ b2i) {
  extern __shared__ char smraw[];
  uint16_t* Asu = (uint16_t*)(smraw + OFF_AS);
  uint16_t* W1u = (uint16_t*)(smraw + OFF_W1);
  uint16_t* W2u = (uint16_t*)(smraw + OFF_W2);
  float* b1s = (float*)(smraw + OFF_B1);
  float* b2s = (float*)(smraw + OFF_B2);

  const int t = threadIdx.x, wid = t >> 5, lane = t & 31;
  const int b = blockIdx.y, nb = blockIdx.z;

  // weights (pre-expanded bf16) -> smem via uint4
  const __nv_bfloat16* gw = g_Wexp + nb * 73728;
  for (int idx = t; idx < 4608; idx += 256) {
    const int n = idx / 24, c8 = (idx % 24) * 8;
    *(uint4*)(W1u + n * KP + c8) = *(const uint4*)(gw + n * 192 + c8);
    *(uint4*)(W2u + n * KP + c8) = *(const uint4*)(gw + 36864 + n * 192 + c8);
  }
  if (t < 192) {
    b1s[t] = (t < 96) ? b1r[nb * 96 + t] : b1i[nb * 96 + t - 96];
    b2s[t] = (t < 96) ? b2r[nb * 96 + t] : b2i[nb * 96 + t - 96];
  }

  const long long chbase = ((long long)b * CC + nb * 96) * MODES;
  const int mwo = (wid & 3) * 32, nwo = (wid >> 2) * 96;
  const int lrow = lane & 15, lcolh = (lane >> 4) * 8;
  const int frow = lane >> 2, fcol = 2 * (lane & 3);
  float* dst = (wid >> 2) ? g_Yi : g_Yr;

  #pragma unroll 1
  for (int it = 0; it < 8; it++) {
    const int m0 = (blockIdx.x * 8 + it) * 128;
    __syncthreads();   // weights ready (it=0) / previous GEMM2 reads done (it>0)
    for (int idx = t; idx < 12288; idx += 256) {
      const int i = idx >> 7, mm = idx & 127;
      const uint32_t u = g_Xb[chbase + (long long)i * MODES + m0 + mm];
      Asu[mm * KP + i]      = (uint16_t)(u & 0xffffu);
      Asu[mm * KP + i + 96] = (uint16_t)(u >> 16);
    }
    __syncthreads();

    float acc[2][12][4];
    gemmPipe(Asu, W1u, mwo, nwo, lrow, lcolh, acc);
    __syncthreads();   // all GEMM1 reads of As done

    #pragma unroll
    for (int mt = 0; mt < 2; mt++)
      #pragma unroll
      for (int nt = 0; nt < 12; nt++) {
        const int col = nwo + nt * 8 + fcol;
        const float bl = b1s[col], bh = b1s[col + 1];
        const int r0 = mwo + mt * 16 + frow;
        __nv_bfloat162 p0, p1;
        p0.x = __float2bfloat16_rn(geluf(acc[mt][nt][0] + bl));
        p0.y = __float2bfloat16_rn(geluf(acc[mt][nt][1] + bh));
        p1.x = __float2bfloat16_rn(geluf(acc[mt][nt][2] + bl));
        p1.y = __float2bfloat16_rn(geluf(acc[mt][nt][3] + bh));
        *(__nv_bfloat162*)(Asu + r0 * KP + col)       = p0;
        *(__nv_bfloat162*)(Asu + (r0 + 8) * KP + col) = p1;
      }
    __syncthreads();   // H1 visible

    gemmPipe(Asu, W2u, mwo, nwo, lrow, lcolh, acc);

    #pragma unroll
    for (int mt = 0; mt < 2; mt++)
      #pragma unroll
      for (int nt = 0; nt < 12; nt++) {
        const int c0 = nt * 8 + fcol;               // channel within half
        const float bl = b2s[nwo + c0], bh = b2s[nwo + c0 + 1];
        const int row = mwo + mt * 16 + frow;
        const long long base = chbase + (long long)c0 * MODES + m0 + row;
        dst[base]             = sshrink(acc[mt][nt][0] + bl);
        dst[base + MODES]     = sshrink(acc[mt][nt][1] + bh);
        dst[base + 8]         = sshrink(acc[mt][nt][2] + bl);
        dst[base + MODES + 8] = sshrink(acc[mt][nt][3] + bh);
      }
  }
}

// ---------------- Pass 5: inverse rFFT along D + residual ----------------
__global__ void __launch_bounds__(256) k_irfft_d(const float* __restrict__ x,
                                                 float* __restrict__ out) {
  __shared__ float sOut[8][32][33];
  const int t = threadIdx.x, warp = t >> 5, lane = t & 31;
  const int line0 = blockIdx.x * 256 + warp * 32;
  const int bc = line0 >> 10, h = (line0 >> 5) & 31;
  float2 v[32];
  const long long ib = (long long)bc * MODES + h * 32 + lane;
  #pragma unroll
  for (int k = 0; k < DR; k++)
    v[k] = make_float2(g_Yr[ib + k * 1024], g_Yi[ib + k * 1024]);
  #pragma unroll
  for (int k = DR; k < 32; k++) {
    const float2 z = v[32 - k];
    v[k] = make_float2(z.x, -z.y);
  }
  fft32<true>(v);
  #pragma unroll
  for (int d = 0; d < 32; d++) sOut[warp][lane][d] = v[d].x * S1;
  __syncwarp();
  const long long gb = (long long)line0 * 32;
  #pragma unroll
  for (int r = 0; r < 32; r++)
    out[gb + r * 32 + lane] = sOut[warp][r][lane] + x[gb + r * 32 + lane];
}

// ---------------- launch ----------------
extern "C" void kernel_launch(void* const* d_in, const int* in_sizes, int n_in,
                              void* d_out, int out_size) {
  const float* x   = (const float*)d_in[0];
  const float* w1r = (const float*)d_in[1];
  const float* w1i = (const float*)d_in[2];
  const float* w2r = (const float*)d_in[3];
  const float* w2i = (const float*)d_in[4];
  const float* b1r = (const float*)d_in[5];
  const float* b1i = (const float*)d_in[6];
  const float* b2r = (const float*)d_in[7];
  const float* b2i = (const float*)d_in[8];
  float* out = (float*)d_out;

  const int fftBytes = 8 * 1056 * (int)sizeof(float2);

  cudaFuncSetAttribute(k_fft_wh_fwd,
                       cudaFuncAttributeMaxDynamicSharedMemorySize, fftBytes);
  cudaFuncSetAttribute(k_fft_wh_inv,
                       cudaFuncAttributeMaxDynamicSharedMemorySize, fftBytes);
  cudaFuncSetAttribute(k_cgemm,
                       cudaFuncAttributeMaxDynamicSharedMemorySize, SM_TOTAL);

  k_wprep<<<NBLK, 256>>>(w1r, w1i, w2r, w2i);
  k_rfft_d<<<NLINES / 256, 256>>>(x);
  k_fft_wh_fwd<<<NPLANES / 8, 256, fftBytes>>>();
  dim3 g3(17, 2, NBLK);
  k_cgemm<<<g3, 256, SM_TOTAL>>>(b1r, b1i, b2r, b2i);
  k_fft_wh_inv<<<NPLANES / 8, 256, fftBytes>>>();
  k_irfft_d<<<NLINES / 256, 256>>>(x, out);
}

// round 5
// speedup vs baseline: 3.2657x; 1.0806x over previous
#include <cuda_runtime.h>
#include <cuda_bf16.h>
#include <math.h>
#include <stdint.h>

#define CC 768
#define NBLK 8
#define DR 17
#define MODES 17408              /* 17*32*32, layout [d'][h][w] */
#define NLINES 1572864           /* 2*768*32*32 */
#define NPLANES 26112            /* 1536*17 */
#define S1 0.0055242717280199026f /* 1/sqrt(32768) */
#define LAMBDA 0.01f
#define KP 200                   /* padded bf16 K-stride in smem */

__device__ uint32_t g_Xb[26738688];          /* forward spectrum, bf16x2 */
__device__ float    g_Yr[26738688];          /* MLP output, planar re  */
__device__ float    g_Yi[26738688];          /* MLP output, planar im  */
__device__ __nv_bfloat16 g_Wexp[589824];     /* 8 blocks x 2 mats x 192x192 */

__constant__ float TWC[16] = {
  1.0f, 0.9807852804032304f, 0.9238795325112867f, 0.8314696123025452f,
  0.7071067811865476f, 0.5555702330196022f, 0.3826834323650898f, 0.19509032201612827f,
  0.0f, -0.19509032201612827f, -0.3826834323650898f, -0.5555702330196022f,
  -0.7071067811865476f, -0.8314696123025452f, -0.9238795325112867f, -0.9807852804032304f
};
__constant__ float TWS[16] = {
  0.0f, 0.19509032201612827f, 0.3826834323650898f, 0.5555702330196022f,
  0.7071067811865476f, 0.8314696123025452f, 0.9238795325112867f, 0.9807852804032304f,
  1.0f, 0.9807852804032304f, 0.9238795325112867f, 0.8314696123025452f,
  0.7071067811865476f, 0.5555702330196022f, 0.3826834323650898f, 0.19509032201612827f
};

template<bool INV>
__device__ __forceinline__ void fft32(float2* v) {
  constexpr int br[32] = {0,16,8,24,4,20,12,28,2,18,10,26,6,22,14,30,
                          1,17,9,25,5,21,13,29,3,19,11,27,7,23,15,31};
  #pragma unroll
  for (int i = 0; i < 32; i++) {
    int j = br[i];
    if (j > i) { float2 tmp = v[i]; v[i] = v[j]; v[j] = tmp; }
  }
  #pragma unroll
  for (int s = 1; s <= 5; s++) {
    const int m = 1 << s, hm = m >> 1;
    #pragma unroll
    for (int j = 0; j < hm; j++) {
      const int ti = j << (5 - s);
      const float wr = TWC[ti];
      const float wi = INV ? TWS[ti] : -TWS[ti];
      #pragma unroll
      for (int k = j; k < 32; k += m) {
        float2 a = v[k], b = v[k + hm];
        float tr = fmaf(b.x, wr, -b.y * wi);
        float tq = fmaf(b.x, wi,  b.y * wr);
        v[k]      = make_float2(a.x + tr, a.y + tq);
        v[k + hm] = make_float2(a.x - tr, a.y - tq);
      }
    }
  }
}

// ---------------- weight prep: expand to bf16 once ----------------
__global__ void k_wprep(const float* __restrict__ w1r, const float* __restrict__ w1i,
                        const float* __restrict__ w2r, const float* __restrict__ w2i) {
  const int nb = blockIdx.x, t = threadIdx.x;
  const int wb = nb * 9216;
  __nv_bfloat16* g1 = g_Wexp + nb * 73728;
  __nv_bfloat16* g2 = g1 + 36864;
  for (int idx = t; idx < 9216; idx += 256) {
    const int i = idx / 96, o = idx % 96;
    const float r1v = w1r[wb + idx], i1v = w1i[wb + idx];
    const float r2v = w2r[wb + idx], i2v = w2i[wb + idx];
    g1[o * 192 + i]              = __float2bfloat16_rn(r1v);
    g1[o * 192 + i + 96]         = __float2bfloat16_rn(-i1v);
    g1[(o + 96) * 192 + i]       = __float2bfloat16_rn(i1v);
    g1[(o + 96) * 192 + i + 96]  = __float2bfloat16_rn(r1v);
    g2[o * 192 + i]              = __float2bfloat16_rn(r2v);
    g2[o * 192 + i + 96]         = __float2bfloat16_rn(-i2v);
    g2[(o + 96) * 192 + i]       = __float2bfloat16_rn(i2v);
    g2[(o + 96) * 192 + i + 96]  = __float2bfloat16_rn(r2v);
  }
}

// ---------------- Pass 1: rFFT along D -> bf16 plane-major spectrum ----------------
__global__ void __launch_bounds__(256) k_rfft_d(const float* __restrict__ x) {
  __shared__ float sIn[8][32][33];
  const int t = threadIdx.x, warp = t >> 5, lane = t & 31;
  const int line0 = blockIdx.x * 256 + warp * 32;
  const float* src = x + (long long)line0 * 32;
  #pragma unroll
  for (int r = 0; r < 32; r++) sIn[warp][r][lane] = src[r * 32 + lane];
  __syncwarp();
  float2 v[32];
  #pragma unroll
  for (int d = 0; d < 32; d++) v[d] = make_float2(sIn[warp][lane][d], 0.0f);
  fft32<false>(v);
  const int bc = line0 >> 10, h = (line0 >> 5) & 31;
  const long long ob = (long long)bc * MODES + h * 32 + lane;
  #pragma unroll
  for (int k = 0; k < DR; k++) {
    __nv_bfloat162 pk = __float22bfloat162_rn(make_float2(v[k].x * S1, v[k].y * S1));
    g_Xb[ob + k * 1024] = *(uint32_t*)&pk;
  }
}

// ---------------- Pass 2: forward W+H FFT on bf16 buffer ----------------
__global__ void __launch_bounds__(256) k_fft_wh_fwd() {
  extern __shared__ float2 sm[];
  const int t = threadIdx.x, p = t >> 5, lane = t & 31;
  float2* pl = sm + p * 1056;
  const long long pb = (long long)(blockIdx.x * 8 + p) * 1024;
  #pragma unroll
  for (int i = 0; i < 32; i++) {
    uint32_t u = g_Xb[pb + i * 32 + lane];
    pl[i * 33 + lane] = __bfloat1622float2(*(__nv_bfloat162*)&u);
  }
  __syncwarp();
  float2 v[32];
  #pragma unroll
  for (int w = 0; w < 32; w++) v[w] = pl[lane * 33 + w];
  fft32<false>(v);
  #pragma unroll
  for (int w = 0; w < 32; w++) pl[lane * 33 + w] = v[w];
  __syncwarp();
  #pragma unroll
  for (int h = 0; h < 32; h++) v[h] = pl[h * 33 + lane];
  fft32<false>(v);
  #pragma unroll
  for (int h = 0; h < 32; h++) pl[h * 33 + lane] = v[h];
  __syncwarp();
  #pragma unroll
  for (int i = 0; i < 32; i++) {
    __nv_bfloat162 pk = __float22bfloat162_rn(pl[i * 33 + lane]);
    g_Xb[pb + i * 32 + lane] = *(uint32_t*)&pk;
  }
}

// ---------------- Pass 4: inverse W+H FFT on planar fp32 buffers ----------------
__global__ void __launch_bounds__(256) k_fft_wh_inv() {
  extern __shared__ float2 sm[];
  const int t = threadIdx.x, p = t >> 5, lane = t & 31;
  float2* pl = sm + p * 1056;
  const long long pb = (long long)(blockIdx.x * 8 + p) * 1024;
  #pragma unroll
  for (int i = 0; i < 32; i++)
    pl[i * 33 + lane] = make_float2(g_Yr[pb + i * 32 + lane],
                                    g_Yi[pb + i * 32 + lane]);
  __syncwarp();
  float2 v[32];
  #pragma unroll
  for (int w = 0; w < 32; w++) v[w] = pl[lane * 33 + w];
  fft32<true>(v);
  #pragma unroll
  for (int w = 0; w < 32; w++) pl[lane * 33 + w] = v[w];
  __syncwarp();
  #pragma unroll
  for (int h = 0; h < 32; h++) v[h] = pl[h * 33 + lane];
  fft32<true>(v);
  #pragma unroll
  for (int h = 0; h < 32; h++) pl[h * 33 + lane] = v[h];
  __syncwarp();
  #pragma unroll
  for (int i = 0; i < 32; i++) {
    const float2 o = pl[i * 33 + lane];
    g_Yr[pb + i * 32 + lane] = o.x;
    g_Yi[pb + i * 32 + lane] = o.y;
  }
}

// ---------------- Pass 3: HMMA fused channel MLP (512 thr, 4x4 warps) ----------------
__device__ __forceinline__ float geluf(float v) {
  return 0.5f * v * (1.0f + erff(v * 0.7071067811865476f));
}
__device__ __forceinline__ float sshrink(float v) {
  float a = fabsf(v) - LAMBDA;
  return a > 0.0f ? copysignf(a, v) : 0.0f;
}
__device__ __forceinline__ uint32_t sptr(const void* p) {
  return (uint32_t)__cvta_generic_to_shared(p);
}
__device__ __forceinline__ void ldm4(uint32_t a, uint32_t r[4]) {
  asm volatile("ldmatrix.sync.aligned.m8n8.x4.shared.b16 {%0,%1,%2,%3},[%4];\n"
               : "=r"(r[0]), "=r"(r[1]), "=r"(r[2]), "=r"(r[3]) : "r"(a));
}
__device__ __forceinline__ void mma16816(float* d, const uint32_t* a,
                                         uint32_t b0, uint32_t b1) {
  asm volatile(
    "mma.sync.aligned.m16n8k16.row.col.f32.bf16.bf16.f32 "
    "{%0,%1,%2,%3},{%4,%5,%6,%7},{%8,%9},{%0,%1,%2,%3};\n"
    : "+f"(d[0]), "+f"(d[1]), "+f"(d[2]), "+f"(d[3])
    : "r"(a[0]), "r"(a[1]), "r"(a[2]), "r"(a[3]), "r"(b0), "r"(b1));
}
__device__ __forceinline__ void loadfr(const uint16_t* As, const uint16_t* Ws,
                                       int arow0, int arow1, int wrow, int kc,
                                       uint32_t a[2][4], uint32_t w[3][4]) {
  ldm4(sptr(As + arow0 * KP + kc), a[0]);
  ldm4(sptr(As + arow1 * KP + kc), a[1]);
  #pragma unroll
  for (int p = 0; p < 3; p++)
    ldm4(sptr(Ws + (wrow + p * 16) * KP + kc), w[p]);
}
__device__ __forceinline__ void gemmPipe(const uint16_t* As, const uint16_t* Ws,
                                         int mwo, int nwo, int lrow, int lcolh,
                                         float acc[2][6][4]) {
  #pragma unroll
  for (int mt = 0; mt < 2; mt++)
    #pragma unroll
    for (int nt = 0; nt < 6; nt++)
      #pragma unroll
      for (int e = 0; e < 4; e++) acc[mt][nt][e] = 0.0f;
  const int arow0 = mwo + lrow, arow1 = mwo + 16 + lrow, wrow = nwo + lrow;
  uint32_t a[2][2][4], w[2][3][4];
  loadfr(As, Ws, arow0, arow1, wrow, lcolh, a[0], w[0]);
  #pragma unroll
  for (int ks = 0; ks < 12; ks++) {
    const int cur = ks & 1;
    if (ks < 11)
      loadfr(As, Ws, arow0, arow1, wrow, (ks + 1) * 16 + lcolh,
             a[cur ^ 1], w[cur ^ 1]);
    #pragma unroll
    for (int p = 0; p < 3; p++)
      #pragma unroll
      for (int mt = 0; mt < 2; mt++) {
        mma16816(acc[mt][2 * p],     a[cur][mt], w[cur][p][0], w[cur][p][2]);
        mma16816(acc[mt][2 * p + 1], a[cur][mt], w[cur][p][1], w[cur][p][3]);
      }
  }
}

#define OFF_AS 0
#define OFF_W1 51200
#define OFF_W2 128000
#define OFF_B1 204800
#define OFF_B2 205568
#define SM_TOTAL 206336
#define NTHR 512

__global__ void __launch_bounds__(NTHR, 1) k_cgemm(
    const float* __restrict__ b1r, const float* __restrict__ b1i,
    const float* __restrict__ b2r, const float* __restrict__ b2i) {
  extern __shared__ char smraw[];
  uint16_t* Asu = (uint16_t*)(smraw + OFF_AS);
  uint16_t* W1u = (uint16_t*)(smraw + OFF_W1);
  uint16_t* W2u = (uint16_t*)(smraw + OFF_W2);
  float* b1s = (float*)(smraw + OFF_B1);
  float* b2s = (float*)(smraw + OFF_B2);

  const int t = threadIdx.x, wid = t >> 5, lane = t & 31;
  const int b = blockIdx.y, nb = blockIdx.z;

  // weights (pre-expanded bf16) -> smem via uint4
  const __nv_bfloat16* gw = g_Wexp + nb * 73728;
  for (int idx = t; idx < 4608; idx += NTHR) {
    const int n = idx / 24, c8 = (idx % 24) * 8;
    *(uint4*)(W1u + n * KP + c8) = *(const uint4*)(gw + n * 192 + c8);
    *(uint4*)(W2u + n * KP + c8) = *(const uint4*)(gw + 36864 + n * 192 + c8);
  }
  if (t < 192) {
    b1s[t] = (t < 96) ? b1r[nb * 96 + t] : b1i[nb * 96 + t - 96];
    b2s[t] = (t < 96) ? b2r[nb * 96 + t] : b2i[nb * 96 + t - 96];
  }

  const long long chbase = ((long long)b * CC + nb * 96) * MODES;
  const int mwo = (wid & 3) * 32, nwo = (wid >> 2) * 48;
  const int lrow = lane & 15, lcolh = (lane >> 4) * 8;
  const int frow = lane >> 2, fcol = 2 * (lane & 3);
  float* dst = (nwo >= 96) ? g_Yi : g_Yr;
  const int nh = nwo % 96;                    // column base within half

  #pragma unroll 1
  for (int it = 0; it < 4; it++) {
    const int m0 = (blockIdx.x * 4 + it) * 128;
    __syncthreads();   // weights ready (it=0) / previous GEMM2 reads done (it>0)
    for (int idx = t; idx < 12288; idx += NTHR) {
      const int i = idx >> 7, mm = idx & 127;
      const uint32_t u = g_Xb[chbase + (long long)i * MODES + m0 + mm];
      Asu[mm * KP + i]      = (uint16_t)(u & 0xffffu);
      Asu[mm * KP + i + 96] = (uint16_t)(u >> 16);
    }
    __syncthreads();

    float acc[2][6][4];
    gemmPipe(Asu, W1u, mwo, nwo, lrow, lcolh, acc);
    __syncthreads();   // all GEMM1 reads of As done

    #pragma unroll
    for (int mt = 0; mt < 2; mt++)
      #pragma unroll
      for (int nt = 0; nt < 6; nt++) {
        const int col = nwo + nt * 8 + fcol;
        const float bl = b1s[col], bh = b1s[col + 1];
        const int r0 = mwo + mt * 16 + frow;
        __nv_bfloat162 p0, p1;
        p0.x = __float2bfloat16_rn(geluf(acc[mt][nt][0] + bl));
        p0.y = __float2bfloat16_rn(geluf(acc[mt][nt][1] + bh));
        p1.x = __float2bfloat16_rn(geluf(acc[mt][nt][2] + bl));
        p1.y = __float2bfloat16_rn(geluf(acc[mt][nt][3] + bh));
        *(__nv_bfloat162*)(Asu + r0 * KP + col)       = p0;
        *(__nv_bfloat162*)(Asu + (r0 + 8) * KP + col) = p1;
      }
    __syncthreads();   // H1 visible

    gemmPipe(Asu, W2u, mwo, nwo, lrow, lcolh, acc);

    #pragma unroll
    for (int mt = 0; mt < 2; mt++)
      #pragma unroll
      for (int nt = 0; nt < 6; nt++) {
        const int c0 = nh + nt * 8 + fcol;
        const float bl = b2s[nwo + nt * 8 + fcol], bh = b2s[nwo + nt * 8 + fcol + 1];
        const int row = mwo + mt * 16 + frow;
        const long long base = chbase + (long long)c0 * MODES + m0 + row;
        dst[base]             = sshrink(acc[mt][nt][0] + bl);
        dst[base + MODES]     = sshrink(acc[mt][nt][1] + bh);
        dst[base + 8]         = sshrink(acc[mt][nt][2] + bl);
        dst[base + MODES + 8] = sshrink(acc[mt][nt][3] + bh);
      }
  }
}

// ---------------- Pass 5: inverse rFFT along D + residual ----------------
__global__ void __launch_bounds__(256) k_irfft_d(const float* __restrict__ x,
                                                 float* __restrict__ out) {
  __shared__ float sOut[8][32][33];
  const int t = threadIdx.x, warp = t >> 5, lane = t & 31;
  const int line0 = blockIdx.x * 256 + warp * 32;
  const int bc = line0 >> 10, h = (line0 >> 5) & 31;
  float2 v[32];
  const long long ib = (long long)bc * MODES + h * 32 + lane;
  #pragma unroll
  for (int k = 0; k < DR; k++)
    v[k] = make_float2(g_Yr[ib + k * 1024], g_Yi[ib + k * 1024]);
  #pragma unroll
  for (int k = DR; k < 32; k++) {
    const float2 z = v[32 - k];
    v[k] = make_float2(z.x, -z.y);
  }
  fft32<true>(v);
  #pragma unroll
  for (int d = 0; d < 32; d++) sOut[warp][lane][d] = v[d].x * S1;
  __syncwarp();
  const long long gb = (long long)line0 * 32;
  #pragma unroll
  for (int r = 0; r < 32; r++)
    out[gb + r * 32 + lane] = sOut[warp][r][lane] + x[gb + r * 32 + lane];
}

// ---------------- launch ----------------
extern "C" void kernel_launch(void* const* d_in, const int* in_sizes, int n_in,
                              void* d_out, int out_size) {
  const float* x   = (const float*)d_in[0];
  const float* w1r = (const float*)d_in[1];
  const float* w1i = (const float*)d_in[2];
  const float* w2r = (const float*)d_in[3];
  const float* w2i = (const float*)d_in[4];
  const float* b1r = (const float*)d_in[5];
  const float* b1i = (const float*)d_in[6];
  const float* b2r = (const float*)d_in[7];
  const float* b2i = (const float*)d_in[8];
  float* out = (float*)d_out;

  const int fftBytes = 8 * 1056 * (int)sizeof(float2);

  cudaFuncSetAttribute(k_fft_wh_fwd,
                       cudaFuncAttributeMaxDynamicSharedMemorySize, fftBytes);
  cudaFuncSetAttribute(k_fft_wh_inv,
                       cudaFuncAttributeMaxDynamicSharedMemorySize, fftBytes);
  cudaFuncSetAttribute(k_cgemm,
                       cudaFuncAttributeMaxDynamicSharedMemorySize, SM_TOTAL);

  k_wprep<<<NBLK, 256>>>(w1r, w1i, w2r, w2i);
  k_rfft_d<<<NLINES / 256, 256>>>(x);
  k_fft_wh_fwd<<<NPLANES / 8, 256, fftBytes>>>();
  dim3 g3(34, 2, NBLK);
  k_cgemm<<<g3, NTHR, SM_TOTAL>>>(b1r, b1i, b2r, b2i);
  k_fft_wh_inv<<<NPLANES / 8, 256, fftBytes>>>();
  k_irfft_d<<<NLINES / 256, 256>>>(x, out);
}